// round 3
// baseline (speedup 1.0000x reference)
#include <cuda_runtime.h>
#include <cstdint>

// Problem constants
#define BATCH    8192   // N dimension of the GEMM (out columns)
#define SIZE_IN  2048   // K dimension
#define SIZE_OUT 2048   // M dimension (out rows)

// Tiling
#define BM 128
#define BN 128
#define BK 32
#define AS_STRIDE 136   // 128 + 8 pad -> conflict-free A LDS
#define BS_STRIDE 36    // 32 + 4 pad  -> conflict-free B LDS

#define NSTAGE 2
#define SMEM_FLOATS (NSTAGE * (BK * AS_STRIDE + BN * BS_STRIDE))
#define SMEM_BYTES  (SMEM_FLOATS * 4)

__device__ __forceinline__ void cp_async16(uint32_t dst, const void* src) {
    asm volatile("cp.async.cg.shared.global [%0], [%1], 16;\n" :: "r"(dst), "l"(src));
}
__device__ __forceinline__ void cp_commit() {
    asm volatile("cp.async.commit_group;\n");
}
template <int N>
__device__ __forceinline__ void cp_wait() {
    asm volatile("cp.async.wait_group %0;\n" :: "n"(N));
}
__device__ __forceinline__ uint32_t f2tf32(float x) {
    uint32_t r;
    asm("cvt.rna.tf32.f32 %0, %1;" : "=r"(r) : "f"(x));
    return r;
}

// out[o, b] = sum_k W[k, o] * in[b, k]
// A = W^T (M=o, K=k): A[o,k] = W[k*SIZE_OUT + o]  (contiguous in o)
// B = in^T (K=k, N=b): B[k,b] = in[b*SIZE_IN + k] (contiguous in k)
__global__ __launch_bounds__(256, 2) void sgemm_tf32_kernel(
    const float* __restrict__ in_values,   // [BATCH, SIZE_IN]
    const float* __restrict__ W,           // [SIZE_IN, SIZE_OUT]
    float* __restrict__ out)               // [SIZE_OUT, BATCH]
{
    extern __shared__ float smem[];
    float* As = smem;                                   // [NSTAGE][BK][AS_STRIDE]
    float* Bs = smem + NSTAGE * BK * AS_STRIDE;         // [NSTAGE][BN][BS_STRIDE]

    const int tid  = threadIdx.x;
    const int lane = tid & 31;
    const int warp = tid >> 5;
    const int warpM = warp & 1;        // 0..1 -> 64 rows each
    const int warpN = warp >> 1;       // 0..3 -> 32 cols each
    const int mo = warpM * 64;
    const int no = warpN * 32;
    const int gr = lane >> 2;          // 0..7
    const int qc = lane & 3;           // 0..3

    const int blockM = blockIdx.x * BM;   // M fastest -> L2 reuse of in-tiles
    const int blockN = blockIdx.y * BN;

    const uint32_t asBase = (uint32_t)__cvta_generic_to_shared(As);
    const uint32_t bsBase = (uint32_t)__cvta_generic_to_shared(Bs);

    // ---- global -> shared (cp.async) for one stage ----
    auto load_stage = [&](int s, int kk) {
        // A tile: BK rows of W, each 128 contiguous floats at column blockM
#pragma unroll
        for (int i = 0; i < 4; i++) {
            int idx  = tid + i * 256;          // 0..1023
            int krow = idx >> 5;               // 0..31
            int c4   = (idx & 31) << 2;        // 0..124
            const float* src = W + (size_t)(kk + krow) * SIZE_OUT + blockM + c4;
            uint32_t dst = asBase + (uint32_t)(((s * BK + krow) * AS_STRIDE + c4) * 4);
            cp_async16(dst, src);
        }
        // B tile: BN rows of in (one per output column b), 32 contiguous k each
#pragma unroll
        for (int i = 0; i < 4; i++) {
            int idx = tid + i * 256;
            int b   = idx >> 3;                // 0..127
            int k4  = (idx & 7) << 2;          // 0..28
            const float* src = in_values + (size_t)(blockN + b) * SIZE_IN + kk + k4;
            uint32_t dst = bsBase + (uint32_t)(((s * BN + b) * BS_STRIDE + k4) * 4);
            cp_async16(dst, src);
        }
    };

    float c[4][4][4];
#pragma unroll
    for (int mi = 0; mi < 4; mi++)
#pragma unroll
        for (int ni = 0; ni < 4; ni++)
#pragma unroll
            for (int r = 0; r < 4; r++) c[mi][ni][r] = 0.0f;

    // Prologue: fill both stages
    load_stage(0, 0);  cp_commit();
    load_stage(1, BK); cp_commit();
    cp_wait<1>();
    __syncthreads();

    int s = 0;
    for (int kk = 0; kk < SIZE_IN; kk += BK) {
        const float* AsS = As + s * BK * AS_STRIDE;
        const float* BsS = Bs + s * BN * BS_STRIDE;

#pragma unroll
        for (int ks = 0; ks < BK / 8; ks++) {
            const int k0 = ks * 8;
            uint32_t af[4][4];
            uint32_t bf[4][2];
#pragma unroll
            for (int mi = 0; mi < 4; mi++) {
                int row = mo + mi * 16 + gr;
                // a0:(gr, qc) a1:(gr+8, qc) a2:(gr, qc+4) a3:(gr+8, qc+4)
                af[mi][0] = f2tf32(AsS[(k0 + qc)     * AS_STRIDE + row]);
                af[mi][1] = f2tf32(AsS[(k0 + qc)     * AS_STRIDE + row + 8]);
                af[mi][2] = f2tf32(AsS[(k0 + qc + 4) * AS_STRIDE + row]);
                af[mi][3] = f2tf32(AsS[(k0 + qc + 4) * AS_STRIDE + row + 8]);
            }
#pragma unroll
            for (int ni = 0; ni < 4; ni++) {
                int col = no + ni * 8 + gr;
                // b0:(k=qc, n=gr) b1:(k=qc+4, n=gr)
                bf[ni][0] = f2tf32(BsS[col * BS_STRIDE + k0 + qc]);
                bf[ni][1] = f2tf32(BsS[col * BS_STRIDE + k0 + qc + 4]);
            }
#pragma unroll
            for (int mi = 0; mi < 4; mi++)
#pragma unroll
                for (int ni = 0; ni < 4; ni++) {
                    asm volatile(
                        "mma.sync.aligned.m16n8k8.row.col.f32.tf32.tf32.f32 "
                        "{%0,%1,%2,%3}, {%4,%5,%6,%7}, {%8,%9}, {%0,%1,%2,%3};\n"
                        : "+f"(c[mi][ni][0]), "+f"(c[mi][ni][1]),
                          "+f"(c[mi][ni][2]), "+f"(c[mi][ni][3])
                        : "r"(af[mi][0]), "r"(af[mi][1]), "r"(af[mi][2]), "r"(af[mi][3]),
                          "r"(bf[ni][0]), "r"(bf[ni][1]));
                }
        }

        __syncthreads();   // everyone done reading stage s
        if (kk + 2 * BK < SIZE_IN) {
            load_stage(s, kk + 2 * BK);
            cp_commit();
            cp_wait<1>();  // stage s^1 (kk+BK) is complete
        } else {
            cp_wait<0>();
        }
        __syncthreads();   // make next stage visible to all
        s ^= 1;
    }

    // Epilogue: direct stores. c0,c1 at (row, 2qc..2qc+1); c2,c3 at (row+8, ...)
#pragma unroll
    for (int mi = 0; mi < 4; mi++) {
#pragma unroll
        for (int ni = 0; ni < 4; ni++) {
            int row = blockM + mo + mi * 16 + gr;
            int col = blockN + no + ni * 8 + qc * 2;
            float2 v0 = make_float2(c[mi][ni][0], c[mi][ni][1]);
            float2 v1 = make_float2(c[mi][ni][2], c[mi][ni][3]);
            *reinterpret_cast<float2*>(&out[(size_t)row * BATCH + col])       = v0;
            *reinterpret_cast<float2*>(&out[(size_t)(row + 8) * BATCH + col]) = v1;
        }
    }
}

extern "C" void kernel_launch(void* const* d_in, const int* in_sizes, int n_in,
                              void* d_out, int out_size) {
    const float* in_values = (const float*)d_in[0];  // [8192, 2048]
    const float* weights   = (const float*)d_in[1];  // [2048, 2048]
    // d_in[2] = bias: intentionally unused (reference discards it)
    float* out = (float*)d_out;                      // [2048, 8192]

    (void)cudaFuncSetAttribute(sgemm_tf32_kernel,
                               cudaFuncAttributeMaxDynamicSharedMemorySize, SMEM_BYTES);

    dim3 grid(SIZE_OUT / BM, BATCH / BN);  // (16, 64): M fastest for L2 reuse
    sgemm_tf32_kernel<<<grid, 256, SMEM_BYTES>>>(in_values, weights, out);
}

// round 5
// speedup vs baseline: 1.0160x; 1.0160x over previous
#include <cuda_runtime.h>
#include <cstdint>

#define BATCH    8192   // N of GEMM
#define SIZE_IN  2048   // K
#define SIZE_OUT 2048   // M

// ---------------- tf32 pre-converted scratch (static device memory) ----------------
__device__ float g_in_t[(size_t)BATCH * SIZE_IN];     // 64 MB
__device__ float g_w_t[(size_t)SIZE_IN * SIZE_OUT];   // 16 MB

__device__ __forceinline__ uint32_t f2tf32(float x) {
    uint32_t r;
    asm("cvt.rna.tf32.f32 %0, %1;" : "=r"(r) : "f"(x));
    return r;
}

__global__ __launch_bounds__(256) void cvt_tf32_kernel(
    const float* __restrict__ src, float* __restrict__ dst, int n4)
{
    int i = blockIdx.x * blockDim.x + threadIdx.x;
    if (i >= n4) return;
    float4 v = reinterpret_cast<const float4*>(src)[i];
    uint4 o;
    o.x = f2tf32(v.x); o.y = f2tf32(v.y); o.z = f2tf32(v.z); o.w = f2tf32(v.w);
    reinterpret_cast<uint4*>(dst)[i] = o;
}

// ---------------- GEMM ----------------
#define BM 128
#define BN 128
#define BK 32
#define AS_STRIDE 136   // 128 + 8 pad
#define BS_STRIDE 36    // 32 + 4 pad
#define NSTAGE 3
#define STAGE_FLOATS (BK * AS_STRIDE + BN * BS_STRIDE)
#define SMEM_BYTES (NSTAGE * STAGE_FLOATS * 4)

__device__ __forceinline__ void cp_async16(uint32_t dst, const void* src) {
    asm volatile("cp.async.cg.shared.global [%0], [%1], 16;\n" :: "r"(dst), "l"(src));
}
__device__ __forceinline__ void cp_commit() {
    asm volatile("cp.async.commit_group;\n");
}
template <int N>
__device__ __forceinline__ void cp_wait() {
    asm volatile("cp.async.wait_group %0;\n" :: "n"(N));
}

// out[o, b] = sum_k W[k, o] * in[b, k]
// A[o,k] = Wt[k*SIZE_OUT + o] (o contiguous), B[k,b] = int[b*SIZE_IN + k] (k contiguous)
__global__ __launch_bounds__(128, 2) void sgemm_tf32_kernel(
    const float* __restrict__ in_t,   // [BATCH, SIZE_IN], tf32-valued
    const float* __restrict__ W_t,    // [SIZE_IN, SIZE_OUT], tf32-valued
    float* __restrict__ out)          // [SIZE_OUT, BATCH]
{
    extern __shared__ float smem[];
    float* As = smem;                              // [NSTAGE][BK][AS_STRIDE]
    float* Bs = smem + NSTAGE * BK * AS_STRIDE;    // [NSTAGE][BN][BS_STRIDE]

    const int tid  = threadIdx.x;     // 0..127, 4 warps
    const int lane = tid & 31;
    const int warp = tid >> 5;
    const int mo = (warp & 1) * 64;   // warp M offset (2 warps over M)
    const int no = (warp >> 1) * 64;  // warp N offset (2 warps over N)
    const int gr = lane >> 2;         // 0..7
    const int qc = lane & 3;          // 0..3

    const int blockM = blockIdx.x * BM;   // M fastest -> W stays L2-resident
    const int blockN = blockIdx.y * BN;

    const uint32_t asBase = (uint32_t)__cvta_generic_to_shared(As);
    const uint32_t bsBase = (uint32_t)__cvta_generic_to_shared(Bs);

    auto load_stage = [&](int s, int kk) {
        // A tile: BK k-rows x 128 contiguous o-floats of W_t
#pragma unroll
        for (int j = 0; j < 8; j++) {
            int idx  = j * 128 + tid;          // 0..1023
            int krow = idx >> 5;               // 0..31
            int c4   = (idx & 31) << 2;        // 0..124
            const float* src = W_t + (size_t)(kk + krow) * SIZE_OUT + blockM + c4;
            cp_async16(asBase + (uint32_t)(((s * BK + krow) * AS_STRIDE + c4) * 4), src);
        }
        // B tile: BN b-rows x 32 contiguous k-floats of in_t
#pragma unroll
        for (int j = 0; j < 8; j++) {
            int idx = j * 128 + tid;           // 0..1023
            int b   = idx >> 3;                // 0..127
            int k4  = (idx & 7) << 2;          // 0..28
            const float* src = in_t + (size_t)(blockN + b) * SIZE_IN + kk + k4;
            cp_async16(bsBase + (uint32_t)(((s * BN + b) * BS_STRIDE + k4) * 4), src);
        }
    };

    float c[4][8][4];
#pragma unroll
    for (int mi = 0; mi < 4; mi++)
#pragma unroll
        for (int ni = 0; ni < 8; ni++)
#pragma unroll
            for (int r = 0; r < 4; r++) c[mi][ni][r] = 0.0f;

    // Prologue: stages 0 and 1 in flight
    load_stage(0, 0);  cp_commit();
    load_stage(1, BK); cp_commit();

    const int NIT = SIZE_IN / BK;   // 64
    for (int i = 0; i < NIT; i++) {
        cp_wait<1>();        // this thread's group for stage i complete
        __syncthreads();     // all threads' stage-i data visible; stage i-1 readers done

        if (i + 2 < NIT) load_stage((i + 2) % NSTAGE, (i + 2) * BK);
        cp_commit();         // always commit (empty groups keep accounting simple)

        const uint32_t* AsU = reinterpret_cast<const uint32_t*>(As + (i % NSTAGE) * BK * AS_STRIDE);
        const uint32_t* BsU = reinterpret_cast<const uint32_t*>(Bs + (i % NSTAGE) * BN * BS_STRIDE);

#pragma unroll
        for (int ks = 0; ks < BK / 8; ks++) {
            const int k0 = ks * 8;
            uint32_t af[4][4];
            uint32_t bf[8][2];
#pragma unroll
            for (int mi = 0; mi < 4; mi++) {
                int row = mo + mi * 16 + gr;
                af[mi][0] = AsU[(k0 + qc)     * AS_STRIDE + row];
                af[mi][1] = AsU[(k0 + qc)     * AS_STRIDE + row + 8];
                af[mi][2] = AsU[(k0 + qc + 4) * AS_STRIDE + row];
                af[mi][3] = AsU[(k0 + qc + 4) * AS_STRIDE + row + 8];
            }
#pragma unroll
            for (int ni = 0; ni < 8; ni++) {
                int col = no + ni * 8 + gr;
                bf[ni][0] = BsU[col * BS_STRIDE + k0 + qc];
                bf[ni][1] = BsU[col * BS_STRIDE + k0 + qc + 4];
            }
#pragma unroll
            for (int mi = 0; mi < 4; mi++)
#pragma unroll
                for (int ni = 0; ni < 8; ni++) {
                    asm volatile(
                        "mma.sync.aligned.m16n8k8.row.col.f32.tf32.tf32.f32 "
                        "{%0,%1,%2,%3}, {%4,%5,%6,%7}, {%8,%9}, {%0,%1,%2,%3};\n"
                        : "+f"(c[mi][ni][0]), "+f"(c[mi][ni][1]),
                          "+f"(c[mi][ni][2]), "+f"(c[mi][ni][3])
                        : "r"(af[mi][0]), "r"(af[mi][1]), "r"(af[mi][2]), "r"(af[mi][3]),
                          "r"(bf[ni][0]), "r"(bf[ni][1]));
                }
        }
    }

    // Epilogue: c0,c1 -> (row, 2qc..2qc+1); c2,c3 -> (row+8, ...)
#pragma unroll
    for (int mi = 0; mi < 4; mi++) {
#pragma unroll
        for (int ni = 0; ni < 8; ni++) {
            int row = blockM + mo + mi * 16 + gr;
            int col = blockN + no + ni * 8 + qc * 2;
            float2 v0 = make_float2(c[mi][ni][0], c[mi][ni][1]);
            float2 v1 = make_float2(c[mi][ni][2], c[mi][ni][3]);
            *reinterpret_cast<float2*>(&out[(size_t)row * BATCH + col])       = v0;
            *reinterpret_cast<float2*>(&out[(size_t)(row + 8) * BATCH + col]) = v1;
        }
    }
}

extern "C" void kernel_launch(void* const* d_in, const int* in_sizes, int n_in,
                              void* d_out, int out_size) {
    const float* in_values = (const float*)d_in[0];  // [8192, 2048]
    const float* weights   = (const float*)d_in[1];  // [2048, 2048]
    // d_in[2] = bias: intentionally unused (reference discards it)
    float* out = (float*)d_out;                      // [2048, 8192]

    float *in_t = nullptr, *w_t = nullptr;
    (void)cudaGetSymbolAddress((void**)&in_t, g_in_t);
    (void)cudaGetSymbolAddress((void**)&w_t,  g_w_t);

    // Prepass: RNA-round both operands to tf32-valued fp32 (main loop cvt-free)
    {
        int n4_in = (BATCH * SIZE_IN) / 4;       // 4,194,304
        int n4_w  = (SIZE_IN * SIZE_OUT) / 4;    // 1,048,576
        cvt_tf32_kernel<<<(n4_in + 255) / 256, 256>>>(in_values, in_t, n4_in);
        cvt_tf32_kernel<<<(n4_w  + 255) / 256, 256>>>(weights,   w_t,  n4_w);
    }

    (void)cudaFuncSetAttribute(sgemm_tf32_kernel,
                               cudaFuncAttributeMaxDynamicSharedMemorySize, SMEM_BYTES);

    dim3 grid(SIZE_OUT / BM, BATCH / BN);  // (16, 64): M fastest for L2 reuse
    sgemm_tf32_kernel<<<grid, 128, SMEM_BYTES>>>(in_t, w_t, out);
}

// round 8
// speedup vs baseline: 1.0863x; 1.0692x over previous
#include <cuda_runtime.h>
#include <cstdint>

#define BATCH    8192   // N of GEMM
#define SIZE_IN  2048   // K
#define SIZE_OUT 2048   // M

// ---------------- tf32 pre-converted scratch (static device memory) ----------------
__device__ float g_in_t[(size_t)BATCH * SIZE_IN];     // 64 MB
__device__ float g_w_t[(size_t)SIZE_IN * SIZE_OUT];   // 16 MB

__device__ __forceinline__ uint32_t f2tf32(float x) {
    uint32_t r;
    asm("cvt.rna.tf32.f32 %0, %1;" : "=r"(r) : "f"(x));
    return r;
}

#define N4_IN ((BATCH * SIZE_IN) / 4)        // 4,194,304
#define N4_W  ((SIZE_IN * SIZE_OUT) / 4)     // 1,048,576

__global__ __launch_bounds__(256) void cvt_tf32_both(
    const float* __restrict__ in_v, const float* __restrict__ w_v,
    float* __restrict__ in_t, float* __restrict__ w_t)
{
    int i = blockIdx.x * blockDim.x + threadIdx.x;
    const float4* src;
    uint4* dst;
    if (i < N4_IN) {
        src = reinterpret_cast<const float4*>(in_v) + i;
        dst = reinterpret_cast<uint4*>(in_t) + i;
    } else {
        int j = i - N4_IN;
        if (j >= N4_W) return;
        src = reinterpret_cast<const float4*>(w_v) + j;
        dst = reinterpret_cast<uint4*>(w_t) + j;
    }
    float4 v = *src;
    uint4 o;
    o.x = f2tf32(v.x); o.y = f2tf32(v.y); o.z = f2tf32(v.z); o.w = f2tf32(v.w);
    *dst = o;
}

// ---------------- GEMM ----------------
#define BM 128
#define BN 128
#define BK 32
#define AS_STRIDE 136   // 128 + 8 pad
#define BS_STRIDE 36    // 32 + 4 pad
#define NSTAGE 2
#define STAGE_FLOATS (BK * AS_STRIDE + BN * BS_STRIDE)   // 8960
#define SMEM_BYTES (NSTAGE * STAGE_FLOATS * 4)           // 71680 -> 3 CTAs = 210KB

__device__ __forceinline__ void cp_async16(uint32_t dst, const void* src) {
    asm volatile("cp.async.cg.shared.global [%0], [%1], 16;\n" :: "r"(dst), "l"(src));
}
__device__ __forceinline__ void cp_commit() {
    asm volatile("cp.async.commit_group;\n");
}
template <int N>
__device__ __forceinline__ void cp_wait() {
    asm volatile("cp.async.wait_group %0;\n" :: "n"(N));
}

// out[o, b] = sum_k W[k, o] * in[b, k]
// A[o,k] = W_t[k*SIZE_OUT + o] (o contiguous), B[k,b] = in_t[b*SIZE_IN + k] (k contiguous)
__global__ __launch_bounds__(128, 3) void sgemm_tf32_kernel(
    const float* __restrict__ in_t,   // [BATCH, SIZE_IN], tf32-valued
    const float* __restrict__ W_t,    // [SIZE_IN, SIZE_OUT], tf32-valued
    float* __restrict__ out)          // [SIZE_OUT, BATCH]
{
    extern __shared__ float smem[];
    float* As = smem;                              // [NSTAGE][BK][AS_STRIDE]
    float* Bs = smem + NSTAGE * BK * AS_STRIDE;    // [NSTAGE][BN][BS_STRIDE]

    const int tid  = threadIdx.x;     // 0..127, 4 warps
    const int lane = tid & 31;
    const int warp = tid >> 5;
    const int mo = (warp & 1) * 64;   // 2 warps over M
    const int no = (warp >> 1) * 64;  // 2 warps over N
    const int gr = lane >> 2;         // 0..7
    const int qc = lane & 3;          // 0..3

    const int blockM = blockIdx.x * BM;   // M fastest -> W stays L2-resident
    const int blockN = blockIdx.y * BN;

    const uint32_t asBase = (uint32_t)__cvta_generic_to_shared(As);
    const uint32_t bsBase = (uint32_t)__cvta_generic_to_shared(Bs);

    auto load_stage = [&](int s, int kk) {
        // A tile: BK k-rows x 128 contiguous o-floats of W_t
#pragma unroll
        for (int j = 0; j < 8; j++) {
            int idx  = j * 128 + tid;          // 0..1023
            int krow = idx >> 5;               // 0..31
            int c4   = (idx & 31) << 2;        // 0..124
            const float* src = W_t + (size_t)(kk + krow) * SIZE_OUT + blockM + c4;
            cp_async16(asBase + (uint32_t)(((s * BK + krow) * AS_STRIDE + c4) * 4), src);
        }
        // B tile: BN b-rows x 32 contiguous k-floats of in_t
#pragma unroll
        for (int j = 0; j < 8; j++) {
            int idx = j * 128 + tid;           // 0..1023
            int b   = idx >> 3;                // 0..127
            int k4  = (idx & 7) << 2;          // 0..28
            const float* src = in_t + (size_t)(blockN + b) * SIZE_IN + kk + k4;
            cp_async16(bsBase + (uint32_t)(((s * BN + b) * BS_STRIDE + k4) * 4), src);
        }
    };

    float c[4][8][4];
#pragma unroll
    for (int mi = 0; mi < 4; mi++)
#pragma unroll
        for (int ni = 0; ni < 8; ni++)
#pragma unroll
            for (int r = 0; r < 4; r++) c[mi][ni][r] = 0.0f;

    // Prologue: both stages in flight
    load_stage(0, 0);  cp_commit();
    load_stage(1, BK); cp_commit();

    const int NIT = SIZE_IN / BK;   // 64
    for (int i = 0; i < NIT; i++) {
        const int s = i & 1;
        cp_wait<1>();        // stage i's group complete (only i+1's may pend)
        __syncthreads();     // stage-i data visible to all warps

        const uint32_t* AsU = reinterpret_cast<const uint32_t*>(As + s * BK * AS_STRIDE);
        const uint32_t* BsU = reinterpret_cast<const uint32_t*>(Bs + s * BN * BS_STRIDE);

#pragma unroll
        for (int ks = 0; ks < BK / 8; ks++) {
            const int k0 = ks * 8;
            uint32_t af[4][4];
            uint32_t bf[8][2];
#pragma unroll
            for (int mi = 0; mi < 4; mi++) {
                int row = mo + mi * 16 + gr;
                af[mi][0] = AsU[(k0 + qc)     * AS_STRIDE + row];
                af[mi][1] = AsU[(k0 + qc)     * AS_STRIDE + row + 8];
                af[mi][2] = AsU[(k0 + qc + 4) * AS_STRIDE + row];
                af[mi][3] = AsU[(k0 + qc + 4) * AS_STRIDE + row + 8];
            }
#pragma unroll
            for (int ni = 0; ni < 8; ni++) {
                int col = no + ni * 8 + gr;
                bf[ni][0] = BsU[col * BS_STRIDE + k0 + qc];
                bf[ni][1] = BsU[col * BS_STRIDE + k0 + qc + 4];
            }
#pragma unroll
            for (int mi = 0; mi < 4; mi++)
#pragma unroll
                for (int ni = 0; ni < 8; ni++) {
                    asm volatile(
                        "mma.sync.aligned.m16n8k8.row.col.f32.tf32.tf32.f32 "
                        "{%0,%1,%2,%3}, {%4,%5,%6,%7}, {%8,%9}, {%0,%1,%2,%3};\n"
                        : "+f"(c[mi][ni][0]), "+f"(c[mi][ni][1]),
                          "+f"(c[mi][ni][2]), "+f"(c[mi][ni][3])
                        : "r"(af[mi][0]), "r"(af[mi][1]), "r"(af[mi][2]), "r"(af[mi][3]),
                          "r"(bf[ni][0]), "r"(bf[ni][1]));
                }
        }

        __syncthreads();     // all warps done reading stage i before its buffer is refilled
        if (i + 2 < NIT) load_stage(s, (i + 2) * BK);
        cp_commit();         // always commit: group accounting stays uniform
    }

    // Epilogue: c0,c1 -> (row, 2qc..2qc+1); c2,c3 -> (row+8, ...)
#pragma unroll
    for (int mi = 0; mi < 4; mi++) {
#pragma unroll
        for (int ni = 0; ni < 8; ni++) {
            int row = blockM + mo + mi * 16 + gr;
            int col = blockN + no + ni * 8 + qc * 2;
            float2 v0 = make_float2(c[mi][ni][0], c[mi][ni][1]);
            float2 v1 = make_float2(c[mi][ni][2], c[mi][ni][3]);
            *reinterpret_cast<float2*>(&out[(size_t)row * BATCH + col])       = v0;
            *reinterpret_cast<float2*>(&out[(size_t)(row + 8) * BATCH + col]) = v1;
        }
    }
}

extern "C" void kernel_launch(void* const* d_in, const int* in_sizes, int n_in,
                              void* d_out, int out_size) {
    const float* in_values = (const float*)d_in[0];  // [8192, 2048]
    const float* weights   = (const float*)d_in[1];  // [2048, 2048]
    // d_in[2] = bias: intentionally unused (reference discards it)
    float* out = (float*)d_out;                      // [2048, 8192]

    float *in_t = nullptr, *w_t = nullptr;
    (void)cudaGetSymbolAddress((void**)&in_t, g_in_t);
    (void)cudaGetSymbolAddress((void**)&w_t,  g_w_t);

    // Prepass: RNA-round both operands to tf32-valued fp32 (single fused launch)
    {
        int n4 = N4_IN + N4_W;                    // 5,242,880
        cvt_tf32_both<<<(n4 + 255) / 256, 256>>>(in_values, weights, in_t, w_t);
    }

    (void)cudaFuncSetAttribute(sgemm_tf32_kernel,
                               cudaFuncAttributeMaxDynamicSharedMemorySize, SMEM_BYTES);

    dim3 grid(SIZE_OUT / BM, BATCH / BN);  // (16, 64): M fastest for L2 reuse
    sgemm_tf32_kernel<<<grid, 128, SMEM_BYTES>>>(in_t, w_t, out);
}

// round 11
// speedup vs baseline: 1.6454x; 1.5146x over previous
#include <cuda_runtime.h>
#include <cuda_fp16.h>
#include <cstdint>

#define BATCH    8192   // N of GEMM
#define SIZE_IN  2048   // K
#define SIZE_OUT 2048   // M

// ---------------- fp16 pre-converted scratch (static device memory) ----------------
__device__ __half g_in_h[(size_t)BATCH * SIZE_IN];      // 32 MB, [b][k] k-contiguous
__device__ __half g_w_h[(size_t)SIZE_OUT * SIZE_IN];    // 8 MB,  [o][k] k-contiguous (W transposed)

__device__ __forceinline__ uint32_t h2_bits(__half2 h) {
    return reinterpret_cast<uint32_t&>(h);
}

// in: elementwise f32 -> fp16, layout preserved
__global__ __launch_bounds__(256) void cvt_in_kernel(
    const float* __restrict__ src, __half* __restrict__ dst)
{
    int i = blockIdx.x * blockDim.x + threadIdx.x;          // one thread = 8 elements
    if (i >= (BATCH * SIZE_IN) / 8) return;
    const float4* s = reinterpret_cast<const float4*>(src) + i * 2;
    float4 v0 = s[0], v1 = s[1];
    uint4 o;
    o.x = h2_bits(__floats2half2_rn(v0.x, v0.y));
    o.y = h2_bits(__floats2half2_rn(v0.z, v0.w));
    o.z = h2_bits(__floats2half2_rn(v1.x, v1.y));
    o.w = h2_bits(__floats2half2_rn(v1.z, v1.w));
    reinterpret_cast<uint4*>(dst)[i] = o;
}

// W[k][o] f32 -> Wh[o][k] fp16 (tiled transpose via smem)
__global__ __launch_bounds__(256) void transpose_cvt_kernel(
    const float* __restrict__ W, __half* __restrict__ Wh)
{
    __shared__ __half tile[32][33];
    const int tx = threadIdx.x, ty = threadIdx.y;           // (32, 8)
    const int o0 = blockIdx.x * 32, k0 = blockIdx.y * 32;
#pragma unroll
    for (int i = 0; i < 4; i++) {
        int k = ty + i * 8;
        tile[k][tx] = __float2half_rn(W[(size_t)(k0 + k) * SIZE_OUT + o0 + tx]);
    }
    __syncthreads();
#pragma unroll
    for (int i = 0; i < 4; i++) {
        int o = ty + i * 8;
        Wh[(size_t)(o0 + o) * SIZE_IN + k0 + tx] = tile[tx][o];
    }
}

// ---------------- GEMM ----------------
#define BM 128
#define BN 128
#define BK 32
#define ST_H 40          // smem row stride in halves (32 + 8 pad) -> 80B rows (16B aligned)
#define ST_W 20          // stride in 32-bit words
#define NSTAGE 3
#define STAGE_HALVES ((BM + BN) * ST_H)                  // 10240 halves = 20480 B
#define SMEM_BYTES (NSTAGE * STAGE_HALVES * 2)           // 61440 B -> 3 CTAs = 184 KB

__device__ __forceinline__ void cp_async16(uint32_t dst, const void* src) {
    asm volatile("cp.async.cg.shared.global [%0], [%1], 16;\n" :: "r"(dst), "l"(src));
}
__device__ __forceinline__ void cp_commit() {
    asm volatile("cp.async.commit_group;\n");
}
template <int N>
__device__ __forceinline__ void cp_wait() {
    asm volatile("cp.async.wait_group %0;\n" :: "n"(N));
}

// out[o, b] = sum_k Wh[o][k] * in_h[b][k]
__global__ __launch_bounds__(128, 3) void sgemm_fp16_kernel(
    const __half* __restrict__ in_h,   // [BATCH][SIZE_IN]
    const __half* __restrict__ Wh,     // [SIZE_OUT][SIZE_IN]
    float* __restrict__ out)           // [SIZE_OUT, BATCH]
{
    extern __shared__ __half smem[];
    __half* As = smem;                            // [NSTAGE][BM][ST_H]  (o rows, k cols)
    __half* Bs = smem + NSTAGE * BM * ST_H;       // [NSTAGE][BN][ST_H]  (b rows, k cols)

    const int tid  = threadIdx.x;     // 4 warps
    const int lane = tid & 31;
    const int warp = tid >> 5;
    const int mo = (warp & 1) * 64;   // 2 warps over M
    const int no = (warp >> 1) * 64;  // 2 warps over N
    const int gr = lane >> 2;         // 0..7
    const int qc = lane & 3;          // 0..3

    const int blockM = blockIdx.x * BM;   // M fastest -> W stays L2-resident
    const int blockN = blockIdx.y * BN;

    const uint32_t asBase = (uint32_t)__cvta_generic_to_shared(As);
    const uint32_t bsBase = (uint32_t)__cvta_generic_to_shared(Bs);

    auto load_stage = [&](int s, int kk) {
        // A tile: 128 o-rows x 32 k-halves (64B/row = 4 chunks). 512 chunks.
#pragma unroll
        for (int j = 0; j < 4; j++) {
            int idx = j * 128 + tid;           // 0..511
            int row = idx >> 2, c = idx & 3;   // c*8 halves = c*16 bytes
            const __half* src = Wh + (size_t)(blockM + row) * SIZE_IN + kk + c * 8;
            cp_async16(asBase + (uint32_t)((s * BM + row) * ST_H + c * 8) * 2, src);
        }
        // B tile: 128 b-rows x 32 k-halves. 512 chunks.
#pragma unroll
        for (int j = 0; j < 4; j++) {
            int idx = j * 128 + tid;
            int row = idx >> 2, c = idx & 3;
            const __half* src = in_h + (size_t)(blockN + row) * SIZE_IN + kk + c * 8;
            cp_async16(bsBase + (uint32_t)((s * BN + row) * ST_H + c * 8) * 2, src);
        }
    };

    float c[4][8][4];
#pragma unroll
    for (int mi = 0; mi < 4; mi++)
#pragma unroll
        for (int ni = 0; ni < 8; ni++)
#pragma unroll
            for (int r = 0; r < 4; r++) c[mi][ni][r] = 0.0f;

    // Prologue: stages 0,1 in flight (lookahead 2 over 3 buffers)
    load_stage(0, 0);  cp_commit();
    load_stage(1, BK); cp_commit();

    const int NIT = SIZE_IN / BK;   // 64
    for (int i = 0; i < NIT; i++) {
        cp_wait<1>();        // stage i complete (only i+1 pending)
        __syncthreads();     // stage i visible; stage i-1 readers all past

        // refill buffer (i+2)%3 — its last readers were stage i-1, ordered above
        if (i + 2 < NIT) load_stage((i + 2) % NSTAGE, (i + 2) * BK);
        cp_commit();

        const uint32_t* AsU = reinterpret_cast<const uint32_t*>(As + (i % NSTAGE) * BM * ST_H);
        const uint32_t* BsU = reinterpret_cast<const uint32_t*>(Bs + (i % NSTAGE) * BN * ST_H);

#pragma unroll
        for (int ks = 0; ks < BK / 16; ks++) {
            const int kw = ks * 8;          // k offset in 32-bit words
            uint32_t af[4][4];
            uint32_t bf[8][2];
#pragma unroll
            for (int mi = 0; mi < 4; mi++) {
                int row = mo + mi * 16 + gr;
                // reg0:(row,   k=2qc..2qc+1) reg1:(row+8, same) reg2:(row, k+8) reg3:(row+8, k+8)
                af[mi][0] = AsU[row       * ST_W + kw + qc];
                af[mi][1] = AsU[(row + 8) * ST_W + kw + qc];
                af[mi][2] = AsU[row       * ST_W + kw + 4 + qc];
                af[mi][3] = AsU[(row + 8) * ST_W + kw + 4 + qc];
            }
#pragma unroll
            for (int ni = 0; ni < 8; ni++) {
                int col = no + ni * 8 + gr;
                // reg0:(k=2qc..2qc+1, n=col) reg1:(k+8, n=col)
                bf[ni][0] = BsU[col * ST_W + kw + qc];
                bf[ni][1] = BsU[col * ST_W + kw + 4 + qc];
            }
#pragma unroll
            for (int mi = 0; mi < 4; mi++)
#pragma unroll
                for (int ni = 0; ni < 8; ni++) {
                    asm volatile(
                        "mma.sync.aligned.m16n8k16.row.col.f32.f16.f16.f32 "
                        "{%0,%1,%2,%3}, {%4,%5,%6,%7}, {%8,%9}, {%0,%1,%2,%3};\n"
                        : "+f"(c[mi][ni][0]), "+f"(c[mi][ni][1]),
                          "+f"(c[mi][ni][2]), "+f"(c[mi][ni][3])
                        : "r"(af[mi][0]), "r"(af[mi][1]), "r"(af[mi][2]), "r"(af[mi][3]),
                          "r"(bf[ni][0]), "r"(bf[ni][1]));
                }
        }
    }

    // Epilogue: c0,c1 -> (row, 2qc..2qc+1); c2,c3 -> (row+8, ...)
#pragma unroll
    for (int mi = 0; mi < 4; mi++) {
#pragma unroll
        for (int ni = 0; ni < 8; ni++) {
            int row = blockM + mo + mi * 16 + gr;
            int col = blockN + no + ni * 8 + qc * 2;
            float2 v0 = make_float2(c[mi][ni][0], c[mi][ni][1]);
            float2 v1 = make_float2(c[mi][ni][2], c[mi][ni][3]);
            *reinterpret_cast<float2*>(&out[(size_t)row * BATCH + col])       = v0;
            *reinterpret_cast<float2*>(&out[(size_t)(row + 8) * BATCH + col]) = v1;
        }
    }
}

extern "C" void kernel_launch(void* const* d_in, const int* in_sizes, int n_in,
                              void* d_out, int out_size) {
    const float* in_values = (const float*)d_in[0];  // [8192, 2048]
    const float* weights   = (const float*)d_in[1];  // [2048, 2048] = W[k][o]
    // d_in[2] = bias: intentionally unused (reference discards it)
    float* out = (float*)d_out;                      // [2048, 8192]

    __half *in_h = nullptr, *w_h = nullptr;
    (void)cudaGetSymbolAddress((void**)&in_h, g_in_h);
    (void)cudaGetSymbolAddress((void**)&w_h,  g_w_h);

    // Prepass 1: in f32 -> fp16 (layout kept)
    {
        int n = (BATCH * SIZE_IN) / 8;               // 2,097,152 threads
        cvt_in_kernel<<<(n + 255) / 256, 256>>>(in_values, in_h);
    }
    // Prepass 2: W f32 [k][o] -> fp16 [o][k] (tiled transpose)
    {
        dim3 blk(32, 8);
        dim3 grd(SIZE_OUT / 32, SIZE_IN / 32);       // (64, 64)
        transpose_cvt_kernel<<<grd, blk>>>(weights, w_h);
    }

    (void)cudaFuncSetAttribute(sgemm_fp16_kernel,
                               cudaFuncAttributeMaxDynamicSharedMemorySize, SMEM_BYTES);

    dim3 grid(SIZE_OUT / BM, BATCH / BN);  // (16, 64): M fastest for L2 reuse
    sgemm_fp16_kernel<<<grid, 128, SMEM_BYTES>>>(in_h, w_h, out);
}

// round 14
// speedup vs baseline: 1.7904x; 1.0881x over previous
#include <cuda_runtime.h>
#include <cuda_fp16.h>
#include <cstdint>

#define BATCH    8192   // N of GEMM
#define SIZE_IN  2048   // K
#define SIZE_OUT 2048   // M

// ---------------- fp16 pre-converted scratch (static device memory) ----------------
__device__ __half g_in_h[(size_t)BATCH * SIZE_IN];      // 32 MB, [b][k] k-contiguous
__device__ __half g_w_h[(size_t)SIZE_OUT * SIZE_IN];    // 8 MB,  [o][k] k-contiguous (W transposed)

__device__ __forceinline__ uint32_t h2_bits(__half2 h) {
    return reinterpret_cast<uint32_t&>(h);
}

// in: elementwise f32 -> fp16, layout preserved
__global__ __launch_bounds__(256) void cvt_in_kernel(
    const float* __restrict__ src, __half* __restrict__ dst)
{
    int i = blockIdx.x * blockDim.x + threadIdx.x;          // one thread = 8 elements
    if (i >= (BATCH * SIZE_IN) / 8) return;
    const float4* s = reinterpret_cast<const float4*>(src) + i * 2;
    float4 v0 = s[0], v1 = s[1];
    uint4 o;
    o.x = h2_bits(__floats2half2_rn(v0.x, v0.y));
    o.y = h2_bits(__floats2half2_rn(v0.z, v0.w));
    o.z = h2_bits(__floats2half2_rn(v1.x, v1.y));
    o.w = h2_bits(__floats2half2_rn(v1.z, v1.w));
    reinterpret_cast<uint4*>(dst)[i] = o;
}

// W[k][o] f32 -> Wh[o][k] fp16 (tiled transpose via smem)
__global__ __launch_bounds__(256) void transpose_cvt_kernel(
    const float* __restrict__ W, __half* __restrict__ Wh)
{
    __shared__ __half tile[32][33];
    const int tx = threadIdx.x, ty = threadIdx.y;           // (32, 8)
    const int o0 = blockIdx.x * 32, k0 = blockIdx.y * 32;
#pragma unroll
    for (int i = 0; i < 4; i++) {
        int k = ty + i * 8;
        tile[k][tx] = __float2half_rn(W[(size_t)(k0 + k) * SIZE_OUT + o0 + tx]);
    }
    __syncthreads();
#pragma unroll
    for (int i = 0; i < 4; i++) {
        int o = ty + i * 8;
        Wh[(size_t)(o0 + o) * SIZE_IN + k0 + tx] = tile[tx][o];
    }
}

// ---------------- GEMM ----------------
#define BM 128
#define BN 128
#define BK 32
#define ST_H 40          // smem row stride in halves (32 + 8 pad) -> 80B rows
#define ST_W 20          // stride in 32-bit words
#define NSTAGE 3
#define STAGE_HALVES ((BM + BN) * ST_H)                  // 10240 halves = 20480 B
#define SMEM_BYTES (NSTAGE * STAGE_HALVES * 2)           // 61440 B -> 3 CTAs = 184 KB

__device__ __forceinline__ void cp_async16(uint32_t dst, const void* src) {
    asm volatile("cp.async.cg.shared.global [%0], [%1], 16;\n" :: "r"(dst), "l"(src));
}
__device__ __forceinline__ void cp_commit() {
    asm volatile("cp.async.commit_group;\n");
}
template <int N>
__device__ __forceinline__ void cp_wait() {
    asm volatile("cp.async.wait_group %0;\n" :: "n"(N));
}
__device__ __forceinline__ void ldsm_x4(uint32_t& r0, uint32_t& r1, uint32_t& r2,
                                        uint32_t& r3, uint32_t addr) {
    asm volatile("ldmatrix.sync.aligned.m8n8.x4.shared.b16 {%0,%1,%2,%3}, [%4];\n"
                 : "=r"(r0), "=r"(r1), "=r"(r2), "=r"(r3) : "r"(addr));
}

// out[o, b] = sum_k Wh[o][k] * in_h[b][k]
__global__ __launch_bounds__(128, 3) void sgemm_fp16_kernel(
    const __half* __restrict__ in_h,   // [BATCH][SIZE_IN]
    const __half* __restrict__ Wh,     // [SIZE_OUT][SIZE_IN]
    float* __restrict__ out)           // [SIZE_OUT, BATCH]
{
    extern __shared__ __half smem[];
    __half* As = smem;                            // [NSTAGE][BM][ST_H]  (o rows, k cols)
    __half* Bs = smem + NSTAGE * BM * ST_H;       // [NSTAGE][BN][ST_H]  (b rows, k cols)

    const int tid  = threadIdx.x;     // 4 warps
    const int lane = tid & 31;
    const int warp = tid >> 5;
    const int mo = (warp & 1) * 64;   // 2 warps over M
    const int no = (warp >> 1) * 64;  // 2 warps over N
    const int gr = lane >> 2;         // 0..7
    const int qc = lane & 3;          // 0..3

    // ldmatrix per-thread row/col offsets (lane -> matrix slot)
    const int grp = lane >> 3, l8 = lane & 7;
    const int a_row_off = (grp & 1) * 8 + l8;   // +8 rows for matrices 1,3
    const int a_kw_off  = (grp >> 1) * 4;       // +8 halves (4 words) for matrices 2,3
    const int b_row_off = (grp >> 1) * 8 + l8;  // +8 n-rows for matrices 2,3
    const int b_kw_off  = (grp & 1) * 4;        // +8 halves for matrices 1,3

    const int blockM = blockIdx.x * BM;   // M fastest -> W stays L2-resident
    const int blockN = blockIdx.y * BN;

    const uint32_t asBase = (uint32_t)__cvta_generic_to_shared(As);
    const uint32_t bsBase = (uint32_t)__cvta_generic_to_shared(Bs);

    auto load_stage = [&](int s, int kk) {
        // A tile: 128 o-rows x 32 k-halves (64B/row = 4 chunks). 512 chunks.
#pragma unroll
        for (int j = 0; j < 4; j++) {
            int idx = j * 128 + tid;           // 0..511
            int row = idx >> 2, c = idx & 3;   // c*8 halves = c*16 bytes
            const __half* src = Wh + (size_t)(blockM + row) * SIZE_IN + kk + c * 8;
            cp_async16(asBase + (uint32_t)((s * BM + row) * ST_H + c * 8) * 2, src);
        }
        // B tile: 128 b-rows x 32 k-halves. 512 chunks.
#pragma unroll
        for (int j = 0; j < 4; j++) {
            int idx = j * 128 + tid;
            int row = idx >> 2, c = idx & 3;
            const __half* src = in_h + (size_t)(blockN + row) * SIZE_IN + kk + c * 8;
            cp_async16(bsBase + (uint32_t)((s * BN + row) * ST_H + c * 8) * 2, src);
        }
    };

    float c[4][8][4];
#pragma unroll
    for (int mi = 0; mi < 4; mi++)
#pragma unroll
        for (int ni = 0; ni < 8; ni++)
#pragma unroll
            for (int r = 0; r < 4; r++) c[mi][ni][r] = 0.0f;

    // Prologue: stages 0,1 in flight (lookahead 2 over 3 buffers)
    load_stage(0, 0);  cp_commit();
    load_stage(1, BK); cp_commit();

    const int NIT = SIZE_IN / BK;   // 64
    for (int i = 0; i < NIT; i++) {
        cp_wait<1>();        // stage i complete (only i+1 pending)
        __syncthreads();     // stage i visible; stage i-1 readers all past

        // refill buffer (i+2)%3 — its last readers were stage i-1, ordered above
        if (i + 2 < NIT) load_stage((i + 2) % NSTAGE, (i + 2) * BK);
        cp_commit();

        const uint32_t asStage = asBase + (uint32_t)((i % NSTAGE) * BM * ST_H) * 2;
        const uint32_t bsStage = bsBase + (uint32_t)((i % NSTAGE) * BN * ST_H) * 2;

#pragma unroll
        for (int ks = 0; ks < BK / 16; ks++) {
            const int kw = ks * 8;          // k offset in 32-bit words
            uint32_t af[4][4];
            uint32_t bf[8][2];
#pragma unroll
            for (int mi = 0; mi < 4; mi++) {
                // matrices: (m+0,k+0)(m+8,k+0)(m+0,k+8)(m+8,k+8) -> a0..a3
                uint32_t addr = asStage +
                    (uint32_t)(((mo + mi * 16 + a_row_off) * ST_W + kw + a_kw_off) * 4);
                ldsm_x4(af[mi][0], af[mi][1], af[mi][2], af[mi][3], addr);
            }
#pragma unroll
            for (int p = 0; p < 4; p++) {
                // matrices: (n_lo,k_lo)(n_lo,k_hi)(n_hi,k_lo)(n_hi,k_hi)
                uint32_t addr = bsStage +
                    (uint32_t)(((no + p * 16 + b_row_off) * ST_W + kw + b_kw_off) * 4);
                ldsm_x4(bf[2*p][0], bf[2*p][1], bf[2*p+1][0], bf[2*p+1][1], addr);
            }
#pragma unroll
            for (int mi = 0; mi < 4; mi++)
#pragma unroll
                for (int ni = 0; ni < 8; ni++) {
                    asm volatile(
                        "mma.sync.aligned.m16n8k16.row.col.f32.f16.f16.f32 "
                        "{%0,%1,%2,%3}, {%4,%5,%6,%7}, {%8,%9}, {%0,%1,%2,%3};\n"
                        : "+f"(c[mi][ni][0]), "+f"(c[mi][ni][1]),
                          "+f"(c[mi][ni][2]), "+f"(c[mi][ni][3])
                        : "r"(af[mi][0]), "r"(af[mi][1]), "r"(af[mi][2]), "r"(af[mi][3]),
                          "r"(bf[ni][0]), "r"(bf[ni][1]));
                }
        }
    }

    // Epilogue: c0,c1 -> (row, 2qc..2qc+1); c2,c3 -> (row+8, ...)
#pragma unroll
    for (int mi = 0; mi < 4; mi++) {
#pragma unroll
        for (int ni = 0; ni < 8; ni++) {
            int row = blockM + mo + mi * 16 + gr;
            int col = blockN + no + ni * 8 + qc * 2;
            float2 v0 = make_float2(c[mi][ni][0], c[mi][ni][1]);
            float2 v1 = make_float2(c[mi][ni][2], c[mi][ni][3]);
            *reinterpret_cast<float2*>(&out[(size_t)row * BATCH + col])       = v0;
            *reinterpret_cast<float2*>(&out[(size_t)(row + 8) * BATCH + col]) = v1;
        }
    }
}

extern "C" void kernel_launch(void* const* d_in, const int* in_sizes, int n_in,
                              void* d_out, int out_size) {
    const float* in_values = (const float*)d_in[0];  // [8192, 2048]
    const float* weights   = (const float*)d_in[1];  // [2048, 2048] = W[k][o]
    // d_in[2] = bias: intentionally unused (reference discards it)
    float* out = (float*)d_out;                      // [2048, 8192]

    __half *in_h = nullptr, *w_h = nullptr;
    (void)cudaGetSymbolAddress((void**)&in_h, g_in_h);
    (void)cudaGetSymbolAddress((void**)&w_h,  g_w_h);

    // Prepass 1: in f32 -> fp16 (layout kept)
    {
        int n = (BATCH * SIZE_IN) / 8;               // 2,097,152 threads
        cvt_in_kernel<<<(n + 255) / 256, 256>>>(in_values, in_h);
    }
    // Prepass 2: W f32 [k][o] -> fp16 [o][k] (tiled transpose)
    {
        dim3 blk(32, 8);
        dim3 grd(SIZE_OUT / 32, SIZE_IN / 32);       // (64, 64)
        transpose_cvt_kernel<<<grd, blk>>>(weights, w_h);
    }

    (void)cudaFuncSetAttribute(sgemm_fp16_kernel,
                               cudaFuncAttributeMaxDynamicSharedMemorySize, SMEM_BYTES);

    dim3 grid(SIZE_OUT / BM, BATCH / BN);  // (16, 64): M fastest for L2 reuse
    sgemm_fp16_kernel<<<grid, 128, SMEM_BYTES>>>(in_h, w_h, out);
}

// round 15
// speedup vs baseline: 1.9125x; 1.0682x over previous
#include <cuda_runtime.h>
#include <cuda_fp16.h>
#include <cstdint>

#define BATCH    8192   // N of GEMM
#define SIZE_IN  2048   // K
#define SIZE_OUT 2048   // M

// ---------------- fp16 pre-converted scratch (static device memory) ----------------
__device__ __half g_in_h[(size_t)BATCH * SIZE_IN];      // 32 MB, [b][k] k-contiguous
__device__ __half g_w_h[(size_t)SIZE_OUT * SIZE_IN];    // 8 MB,  [o][k] (W transposed)

__device__ __forceinline__ uint32_t h2_bits(__half2 h) {
    return reinterpret_cast<uint32_t&>(h);
}

#define CVT_BLOCKS   8192   // in-cvt blocks (256 thr, 8 elem/thr)
#define TRANS_BLOCKS 4096   // transpose blocks (32x32 tile each)

// Fused prepass: blocks [0,8192) convert in; blocks [8192,12288) transpose-convert W
__global__ __launch_bounds__(256) void prepass_kernel(
    const float* __restrict__ in_v, const float* __restrict__ W,
    __half* __restrict__ in_h, __half* __restrict__ Wh)
{
    if (blockIdx.x < CVT_BLOCKS) {
        int i = blockIdx.x * 256 + threadIdx.x;          // one thread = 8 elements
        const float4* s = reinterpret_cast<const float4*>(in_v) + i * 2;
        float4 v0 = s[0], v1 = s[1];
        uint4 o;
        o.x = h2_bits(__floats2half2_rn(v0.x, v0.y));
        o.y = h2_bits(__floats2half2_rn(v0.z, v0.w));
        o.z = h2_bits(__floats2half2_rn(v1.x, v1.y));
        o.w = h2_bits(__floats2half2_rn(v1.z, v1.w));
        reinterpret_cast<uint4*>(in_h)[i] = o;
    } else {
        __shared__ __half tile[32][33];
        int j  = blockIdx.x - CVT_BLOCKS;
        int tx = threadIdx.x & 31, ty = threadIdx.x >> 5;   // (32, 8)
        int o0 = (j & 63) * 32, k0 = (j >> 6) * 32;
#pragma unroll
        for (int i = 0; i < 4; i++) {
            int k = ty + i * 8;
            tile[k][tx] = __float2half_rn(W[(size_t)(k0 + k) * SIZE_OUT + o0 + tx]);
        }
        __syncthreads();
#pragma unroll
        for (int i = 0; i < 4; i++) {
            int o = ty + i * 8;
            Wh[(size_t)(o0 + o) * SIZE_IN + k0 + tx] = tile[tx][o];
        }
    }
}

// ---------------- GEMM ----------------
#define BM 128
#define BN 128
#define BK 64
#define ST_H 72          // smem row stride in halves (64 + 8 pad) -> 144B rows
#define ST_W 36          // stride in 32-bit words
#define NSTAGE 2
#define STAGE_HALVES ((BM + BN) * ST_H)                  // 18432 halves = 36864 B
#define SMEM_BYTES (NSTAGE * STAGE_HALVES * 2)           // 73728 B -> 2 CTAs = 147 KB

__device__ __forceinline__ void cp_async16(uint32_t dst, const void* src) {
    asm volatile("cp.async.cg.shared.global [%0], [%1], 16;\n" :: "r"(dst), "l"(src));
}
__device__ __forceinline__ void cp_commit() {
    asm volatile("cp.async.commit_group;\n");
}
template <int N>
__device__ __forceinline__ void cp_wait() {
    asm volatile("cp.async.wait_group %0;\n" :: "n"(N));
}
__device__ __forceinline__ void ldsm_x4(uint32_t& r0, uint32_t& r1, uint32_t& r2,
                                        uint32_t& r3, uint32_t addr) {
    asm volatile("ldmatrix.sync.aligned.m8n8.x4.shared.b16 {%0,%1,%2,%3}, [%4];\n"
                 : "=r"(r0), "=r"(r1), "=r"(r2), "=r"(r3) : "r"(addr));
}

// out[o, b] = sum_k Wh[o][k] * in_h[b][k]
__global__ __launch_bounds__(256, 2) void sgemm_fp16_kernel(
    const __half* __restrict__ in_h,   // [BATCH][SIZE_IN]
    const __half* __restrict__ Wh,     // [SIZE_OUT][SIZE_IN]
    float* __restrict__ out)           // [SIZE_OUT, BATCH]
{
    extern __shared__ __half smem[];
    __half* As = smem;                            // [NSTAGE][BM][ST_H]  (o rows, k cols)
    __half* Bs = smem + NSTAGE * BM * ST_H;       // [NSTAGE][BN][ST_H]  (b rows, k cols)

    const int tid  = threadIdx.x;     // 8 warps
    const int lane = tid & 31;
    const int warp = tid >> 5;
    const int mo = (warp & 1) * 64;   // 2 warps over M (64 rows)
    const int no = (warp >> 1) * 32;  // 4 warps over N (32 cols)
    const int gr = lane >> 2;         // 0..7
    const int qc = lane & 3;          // 0..3

    // ldmatrix per-thread offsets (lane -> matrix slot)
    const int grp = lane >> 3, l8 = lane & 7;
    const int a_row_off = (grp & 1) * 8 + l8;   // +8 rows for matrices 1,3
    const int a_kw_off  = (grp >> 1) * 4;       // +8 halves for matrices 2,3
    const int b_row_off = (grp >> 1) * 8 + l8;  // +8 n-rows for matrices 2,3
    const int b_kw_off  = (grp & 1) * 4;        // +8 halves for matrices 1,3

    const int blockM = blockIdx.x * BM;   // M fastest -> W stays L2-resident
    const int blockN = blockIdx.y * BN;

    const uint32_t asBase = (uint32_t)__cvta_generic_to_shared(As);
    const uint32_t bsBase = (uint32_t)__cvta_generic_to_shared(Bs);

    auto load_stage = [&](int s, int kk) {
        // A tile: 128 o-rows x 64 k-halves (128B/row = 8 chunks). 1024 chunks.
#pragma unroll
        for (int j = 0; j < 4; j++) {
            int idx = j * 256 + tid;           // 0..1023
            int row = idx >> 3, c = idx & 7;   // c*8 halves = c*16 bytes
            const __half* src = Wh + (size_t)(blockM + row) * SIZE_IN + kk + c * 8;
            cp_async16(asBase + (uint32_t)((s * BM + row) * ST_H + c * 8) * 2, src);
        }
        // B tile: 128 b-rows x 64 k-halves. 1024 chunks.
#pragma unroll
        for (int j = 0; j < 4; j++) {
            int idx = j * 256 + tid;
            int row = idx >> 3, c = idx & 7;
            const __half* src = in_h + (size_t)(blockN + row) * SIZE_IN + kk + c * 8;
            cp_async16(bsBase + (uint32_t)((s * BN + row) * ST_H + c * 8) * 2, src);
        }
    };

    float c[4][4][4];
#pragma unroll
    for (int mi = 0; mi < 4; mi++)
#pragma unroll
        for (int ni = 0; ni < 4; ni++)
#pragma unroll
            for (int r = 0; r < 4; r++) c[mi][ni][r] = 0.0f;

    // Prologue: both stages in flight
    load_stage(0, 0);  cp_commit();
    load_stage(1, BK); cp_commit();

    const int NIT = SIZE_IN / BK;   // 32
    for (int i = 0; i < NIT; i++) {
        const int s = i & 1;
        cp_wait<1>();        // stage i complete (only i+1 pending)
        __syncthreads();     // stage i visible to all warps

        const uint32_t asStage = asBase + (uint32_t)(s * BM * ST_H) * 2;
        const uint32_t bsStage = bsBase + (uint32_t)(s * BN * ST_H) * 2;

#pragma unroll
        for (int ks = 0; ks < BK / 16; ks++) {
            const int kw = ks * 8;          // k offset in 32-bit words
            uint32_t af[4][4];
            uint32_t bf[4][2];
#pragma unroll
            for (int mi = 0; mi < 4; mi++) {
                // matrices: (m+0,k+0)(m+8,k+0)(m+0,k+8)(m+8,k+8) -> a0..a3
                uint32_t addr = asStage +
                    (uint32_t)(((mo + mi * 16 + a_row_off) * ST_W + kw + a_kw_off) * 4);
                ldsm_x4(af[mi][0], af[mi][1], af[mi][2], af[mi][3], addr);
            }
#pragma unroll
            for (int p = 0; p < 2; p++) {
                // matrices: (n_lo,k_lo)(n_lo,k_hi)(n_hi,k_lo)(n_hi,k_hi)
                uint32_t addr = bsStage +
                    (uint32_t)(((no + p * 16 + b_row_off) * ST_W + kw + b_kw_off) * 4);
                ldsm_x4(bf[2*p][0], bf[2*p][1], bf[2*p+1][0], bf[2*p+1][1], addr);
            }
#pragma unroll
            for (int mi = 0; mi < 4; mi++)
#pragma unroll
                for (int ni = 0; ni < 4; ni++) {
                    asm volatile(
                        "mma.sync.aligned.m16n8k16.row.col.f32.f16.f16.f32 "
                        "{%0,%1,%2,%3}, {%4,%5,%6,%7}, {%8,%9}, {%0,%1,%2,%3};\n"
                        : "+f"(c[mi][ni][0]), "+f"(c[mi][ni][1]),
                          "+f"(c[mi][ni][2]), "+f"(c[mi][ni][3])
                        : "r"(af[mi][0]), "r"(af[mi][1]), "r"(af[mi][2]), "r"(af[mi][3]),
                          "r"(bf[ni][0]), "r"(bf[ni][1]));
                }
        }

        __syncthreads();     // all warps done reading stage i before refill
        if (i + 2 < NIT) load_stage(s, (i + 2) * BK);
        cp_commit();         // uniform group accounting
    }

    // Epilogue: c0,c1 -> (row, 2qc..2qc+1); c2,c3 -> (row+8, ...)
#pragma unroll
    for (int mi = 0; mi < 4; mi++) {
#pragma unroll
        for (int ni = 0; ni < 4; ni++) {
            int row = blockM + mo + mi * 16 + gr;
            int col = blockN + no + ni * 8 + qc * 2;
            float2 v0 = make_float2(c[mi][ni][0], c[mi][ni][1]);
            float2 v1 = make_float2(c[mi][ni][2], c[mi][ni][3]);
            *reinterpret_cast<float2*>(&out[(size_t)row * BATCH + col])       = v0;
            *reinterpret_cast<float2*>(&out[(size_t)(row + 8) * BATCH + col]) = v1;
        }
    }
}

extern "C" void kernel_launch(void* const* d_in, const int* in_sizes, int n_in,
                              void* d_out, int out_size) {
    const float* in_values = (const float*)d_in[0];  // [8192, 2048]
    const float* weights   = (const float*)d_in[1];  // [2048, 2048] = W[k][o]
    // d_in[2] = bias: intentionally unused (reference discards it)
    float* out = (float*)d_out;                      // [2048, 8192]

    __half *in_h = nullptr, *w_h = nullptr;
    (void)cudaGetSymbolAddress((void**)&in_h, g_in_h);
    (void)cudaGetSymbolAddress((void**)&w_h,  g_w_h);

    // Fused prepass: in f32->fp16 + W transpose->fp16
    prepass_kernel<<<CVT_BLOCKS + TRANS_BLOCKS, 256>>>(in_values, weights, in_h, w_h);

    (void)cudaFuncSetAttribute(sgemm_fp16_kernel,
                               cudaFuncAttributeMaxDynamicSharedMemorySize, SMEM_BYTES);

    dim3 grid(SIZE_OUT / BM, BATCH / BN);  // (16, 64): M fastest for L2 reuse
    sgemm_fp16_kernel<<<grid, 256, SMEM_BYTES>>>(in_h, w_h, out);
}